// round 1
// baseline (speedup 1.0000x reference)
#include <cuda_runtime.h>
#include <cstdint>

#define GENE   2000
#define TE     128
#define HID    2048
#define KIN    2128      // GENE + TE
#define NSTEP  256
#define GRID   128
#define BLOCK  512
#define DT     (1.0f/255.0f)

// Persistent scratch (device globals: no allocation allowed)
__device__ float    g_x[2][2048];      // x ping-pong (2000 used)
__device__ float    g_h0[2048];        // activation ping-pong
__device__ float    g_h1[2048];
__device__ float    g_te[NSTEP][TE];   // precomputed time embeddings, t=1..255
__device__ unsigned g_count;           // grid-barrier monotonic counter

// ---------------------------------------------------------------------------
// Grid barrier: monotonic counter, release-arrive + acquire-spin.
// All GRID CTAs are co-resident (GRID <= SM count, 1 CTA/SM), so no deadlock.
// ---------------------------------------------------------------------------
__device__ __forceinline__ void grid_barrier(unsigned& nbar) {
    __syncthreads();
    ++nbar;
    if (threadIdx.x == 0) {
        __threadfence();
        asm volatile("red.release.gpu.add.u32 [%0], 1;" :: "l"(&g_count) : "memory");
        const unsigned target = nbar * GRID;
        unsigned cur;
        do {
            asm volatile("ld.acquire.gpu.u32 %0, [%1];" : "=r"(cur) : "l"(&g_count) : "memory");
        } while (cur < target);
    }
    __syncthreads();
}

// ---------------------------------------------------------------------------
// Layer core: out-tile of 16 columns per CTA (j0), full K walk.
// Threads: tid = kw*4 + jv   (kw in [0,128), jv in [0,4))
//   thread loads float4 of W at column j0+4*jv, rows k = kw, kw+128, ...
// Input vector staged in SMEM (xs). SPLIT: for layer 0, k<SPLIT reads `in`
// (x vector), k>=SPLIT reads `in2` (time embedding). SPLIT==K disables in2.
// Returns final 16-wide tile sums: valid in threads tid<4 (j = j0 + tid*4).
// ---------------------------------------------------------------------------
template<int K, int SPLIT>
__device__ __forceinline__ float4 layer_core(
    const float* __restrict__ W, const int O,
    const float* __restrict__ in, const float* __restrict__ in2,
    float* __restrict__ xs,
    const int j0, const int tid)
{
    // Stage input vector into SMEM (coalesced; .cg to bypass possibly-stale L1)
    for (int k = tid; k < K; k += BLOCK) {
        float v;
        if (SPLIT >= K || k < SPLIT) v = __ldcg(in + k);
        else                         v = __ldcg(in2 + (k - SPLIT));
        xs[k] = v;
    }
    __syncthreads();

    float4 acc = make_float4(0.f, 0.f, 0.f, 0.f);
    if (j0 < O) {
        const int kw = tid >> 2;
        const int jv = tid & 3;
        const float* __restrict__ wbase = W + j0 + 4 * jv;
        #pragma unroll 8
        for (int k = kw; k < K; k += BLOCK / 4) {
            const float  xv = xs[k];
            const float4 w  = __ldg(reinterpret_cast<const float4*>(wbase + (long)k * O));
            acc.x = fmaf(xv, w.x, acc.x);
            acc.y = fmaf(xv, w.y, acc.y);
            acc.z = fmaf(xv, w.z, acc.z);
            acc.w = fmaf(xv, w.w, acc.w);
        }
    }

    // Intra-warp reduce over the 8 kw groups inside each warp (lane bits 2..4)
    #pragma unroll
    for (int m = 4; m <= 16; m <<= 1) {
        acc.x += __shfl_xor_sync(0xffffffffu, acc.x, m);
        acc.y += __shfl_xor_sync(0xffffffffu, acc.y, m);
        acc.z += __shfl_xor_sync(0xffffffffu, acc.z, m);
        acc.w += __shfl_xor_sync(0xffffffffu, acc.w, m);
    }

    __shared__ float4 red[16][4];     // [warp][jv]
    const int warp = tid >> 5;
    const int lane = tid & 31;
    if (lane < 4) red[warp][lane] = acc;
    __syncthreads();

    float4 r = make_float4(0.f, 0.f, 0.f, 0.f);
    if (tid < 32) {                    // warp 0 reduces the 16 warp-partials
        const int wi = tid >> 2;       // 0..7
        const int j  = tid & 3;        // jv
        const float4 a = red[wi][j];
        const float4 b = red[wi + 8][j];
        r.x = a.x + b.x; r.y = a.y + b.y; r.z = a.z + b.z; r.w = a.w + b.w;
        #pragma unroll
        for (int m = 4; m <= 16; m <<= 1) {
            r.x += __shfl_xor_sync(0xffffffffu, r.x, m);
            r.y += __shfl_xor_sync(0xffffffffu, r.y, m);
            r.z += __shfl_xor_sync(0xffffffffu, r.z, m);
            r.w += __shfl_xor_sync(0xffffffffu, r.w, m);
        }
    }
    return r;   // valid for tid < 4
}

template<int K, int SPLIT>
__device__ __forceinline__ void layer_hidden(
    const float* __restrict__ W, const float* __restrict__ bias, const int O,
    const float* __restrict__ in, const float* __restrict__ in2,
    float* __restrict__ out, float* __restrict__ xs,
    const int j0, const int tid)
{
    float4 r = layer_core<K, SPLIT>(W, O, in, in2, xs, j0, tid);
    if (tid < 4 && j0 < O) {
        const float4 b = __ldg(reinterpret_cast<const float4*>(bias + j0 + tid * 4));
        r.x = fmaxf(r.x + b.x, 0.f);
        r.y = fmaxf(r.y + b.y, 0.f);
        r.z = fmaxf(r.z + b.z, 0.f);
        r.w = fmaxf(r.w + b.w, 0.f);
        *reinterpret_cast<float4*>(out + j0 + tid * 4) = r;
    }
}

__device__ __forceinline__ void layer_final(
    const float* __restrict__ W, const float* __restrict__ bias,
    const float* __restrict__ xprev, float* __restrict__ xcur,
    float* __restrict__ traj_row,
    const float* __restrict__ in, float* __restrict__ xs,
    const int j0, const int tid)
{
    float4 r = layer_core<HID, HID>(W, GENE, in, in, xs, j0, tid);
    if (tid < 4 && j0 < GENE) {
        const float4 b  = __ldg(reinterpret_cast<const float4*>(bias + j0 + tid * 4));
        const float4 xp = __ldcg(reinterpret_cast<const float4*>(xprev + j0 + tid * 4));
        float4 xn;
        xn.x = fmaf(r.x + b.x, DT, xp.x);
        xn.y = fmaf(r.y + b.y, DT, xp.y);
        xn.z = fmaf(r.z + b.z, DT, xp.z);
        xn.w = fmaf(r.w + b.w, DT, xp.w);
        *reinterpret_cast<float4*>(xcur + j0 + tid * 4)     = xn;
        *reinterpret_cast<float4*>(traj_row + j0 + tid * 4) = xn;
    }
}

// ---------------------------------------------------------------------------
// Init: reset barrier counter, seed x0 + trajectory row 0, precompute all te.
// Runs before the persistent kernel every call (stream-ordered) -> replay-safe.
// ---------------------------------------------------------------------------
__global__ void init_kernel(
    const float* __restrict__ start,
    const float* __restrict__ te_w1, const float* __restrict__ te_b1,
    const float* __restrict__ te_w2, const float* __restrict__ te_b2,
    float* __restrict__ out)
{
    const int b   = blockIdx.x;     // 0..255
    const int tid = threadIdx.x;    // 128 threads
    if (b == 0) {
        if (tid == 0) g_count = 0u;
        for (int k = tid; k < GENE; k += 128) {
            const float v = start[k];
            g_x[0][k] = v;
            out[k]    = v;          // trajectory row 0
        }
    } else {
        const float t = (float)b * DT;
        __shared__ float h[TE];
        h[tid] = fmaxf(fmaf(t, te_w1[tid], te_b1[tid]), 0.f);
        __syncthreads();
        float acc = te_b2[tid];
        #pragma unroll 8
        for (int k = 0; k < TE; ++k)
            acc = fmaf(h[k], te_w2[k * TE + tid], acc);
        g_te[b][tid] = acc;
    }
}

// ---------------------------------------------------------------------------
// Persistent kernel: 255 Euler steps, 6 grid barriers per step.
// ---------------------------------------------------------------------------
__global__ void __launch_bounds__(BLOCK, 1) bridge_kernel(
    const float* __restrict__ w0, const float* __restrict__ b0,
    const float* __restrict__ w1, const float* __restrict__ b1,
    const float* __restrict__ w2, const float* __restrict__ b2,
    const float* __restrict__ w3, const float* __restrict__ b3,
    const float* __restrict__ w4, const float* __restrict__ b4,
    const float* __restrict__ wout, const float* __restrict__ bout,
    float* __restrict__ out)
{
    __shared__ float xs[KIN];
    const int tid = threadIdx.x;
    const int j0  = blockIdx.x * 16;
    unsigned nbar = 0;

    for (int t = 1; t < NSTEP; ++t) {
        const float* xprev = g_x[(t - 1) & 1];
        float*       xcur  = g_x[t & 1];

        layer_hidden<KIN, GENE>(w0, b0, HID, xprev, g_te[t], g_h0, xs, j0, tid);
        grid_barrier(nbar);
        layer_hidden<HID, HID>(w1, b1, HID, g_h0, g_h0, g_h1, xs, j0, tid);
        grid_barrier(nbar);
        layer_hidden<HID, HID>(w2, b2, HID, g_h1, g_h1, g_h0, xs, j0, tid);
        grid_barrier(nbar);
        layer_hidden<HID, HID>(w3, b3, HID, g_h0, g_h0, g_h1, xs, j0, tid);
        grid_barrier(nbar);
        layer_hidden<HID, HID>(w4, b4, HID, g_h1, g_h1, g_h0, xs, j0, tid);
        grid_barrier(nbar);
        layer_final(wout, bout, xprev, xcur, out + (size_t)t * GENE, g_h0, xs, j0, tid);
        grid_barrier(nbar);
    }
}

extern "C" void kernel_launch(void* const* d_in, const int* in_sizes, int n_in,
                              void* d_out, int out_size)
{
    (void)in_sizes; (void)n_in; (void)out_size;
    const float* start  = (const float*)d_in[0];
    // d_in[1] = end_state (unused)
    const float* te_w1  = (const float*)d_in[2];
    const float* te_b1  = (const float*)d_in[3];
    const float* te_w2  = (const float*)d_in[4];
    const float* te_b2  = (const float*)d_in[5];
    const float* w0     = (const float*)d_in[6];
    const float* b0     = (const float*)d_in[7];
    const float* w1     = (const float*)d_in[8];
    const float* b1     = (const float*)d_in[9];
    const float* w2     = (const float*)d_in[10];
    const float* b2     = (const float*)d_in[11];
    const float* w3     = (const float*)d_in[12];
    const float* b3     = (const float*)d_in[13];
    const float* w4     = (const float*)d_in[14];
    const float* b4     = (const float*)d_in[15];
    const float* wout   = (const float*)d_in[16];
    const float* bout   = (const float*)d_in[17];
    float* out = (float*)d_out;

    init_kernel<<<NSTEP, TE>>>(start, te_w1, te_b1, te_w2, te_b2, out);
    bridge_kernel<<<GRID, BLOCK>>>(w0, b0, w1, b1, w2, b2, w3, b3, w4, b4,
                                   wout, bout, out);
}

// round 2
// speedup vs baseline: 1.0692x; 1.0692x over previous
#include <cuda_runtime.h>
#include <cstdint>

#define GENE   2000
#define TE     128
#define HID    2048
#define KIN    2128      // GENE + TE (time embedding lives in x tail)
#define NSTEP  256
#define GRID   128
#define BLOCK  512
#define DT     (1.0f/255.0f)
#define CHUNK  512                        // weight rows per cp.async chunk
#define SMEM_FLOATS (2176 + 2*CHUNK*16)   // xs + double buffer
#define SMEM_BYTES  (SMEM_FLOATS*4)

// Persistent scratch (device globals: allocation is forbidden)
__device__ float    g_x[2][2176];      // x ping-pong: [0,2000)=x, [2000,2128)=te(t)
__device__ float    g_h0[HID];
__device__ float    g_h1[HID];
__device__ float    g_te[NSTEP][TE];   // precomputed time embeddings
__device__ unsigned g_count;           // grid-barrier monotonic counter

// ---------------------------------------------------------------------------
// Grid barrier: monotonic counter, release-arrive + acquire-spin.
// ---------------------------------------------------------------------------
__device__ __forceinline__ void grid_barrier(unsigned& nbar) {
    __syncthreads();
    ++nbar;
    if (threadIdx.x == 0) {
        __threadfence();
        asm volatile("red.release.gpu.add.u32 [%0], 1;" :: "l"(&g_count) : "memory");
        const unsigned target = nbar * GRID;
        unsigned cur;
        do {
            asm volatile("ld.acquire.gpu.u32 %0, [%1];" : "=r"(cur) : "l"(&g_count) : "memory");
        } while (cur < target);
    }
    __syncthreads();
}

// ---------------------------------------------------------------------------
// cp.async helpers
// ---------------------------------------------------------------------------
__device__ __forceinline__ void cp16(float* dst, const float* src) {
    unsigned a = (unsigned)__cvta_generic_to_shared(dst);
    asm volatile("cp.async.cg.shared.global [%0], [%1], 16;" :: "r"(a), "l"(src));
}

// Prefetch one CHUNK-row x 16-col weight slice into smem buf. All threads
// execute commit_group (uniform group counts) even when the CTA is idle.
__device__ __forceinline__ void prefetch_chunk(const float* __restrict__ W,
        int K, int O, int j0, int base, float* __restrict__ buf, int tid) {
    if (j0 < O) {
        #pragma unroll
        for (int i = 0; i < (CHUNK*4)/BLOCK; ++i) {      // 4 x 16B segments/thread
            int s = tid + i*BLOCK;
            int r = s >> 2, c = s & 3;
            if (base + r < K)
                cp16(buf + r*16 + c*4, W + (long)(base + r)*O + j0 + c*4);
        }
    }
    asm volatile("cp.async.commit_group;");
}

// ---------------------------------------------------------------------------
// Generic layer: grid barrier, stage input to smem, pipelined chunk GEMV.
// On entry chunk0 of THIS layer is already in bufs[slot]; on exit chunk0 of
// the NEXT layer (Wn,Kn,On) is in bufs[slot]. Result valid for tid<4.
// ---------------------------------------------------------------------------
__device__ __forceinline__ float4 layer_core(
    const float* __restrict__ W,  int K,  int O,
    const float* __restrict__ Wn, int Kn, int On,
    const float* __restrict__ in,
    float* __restrict__ xs, float* __restrict__ bufA, float* __restrict__ bufB,
    int& slot, float4 (*red)[4],
    int j0, int tid, unsigned& nbar)
{
    grid_barrier(nbar);

    // Stage input vector (L2 path — produced by other SMs)
    const int K4 = K >> 2;
    for (int i = tid; i < K4; i += BLOCK)
        reinterpret_cast<float4*>(xs)[i] =
            __ldcg(reinterpret_cast<const float4*>(in) + i);

    const int kw = tid >> 2;
    const int jv = tid & 3;
    float4 acc = make_float4(0.f, 0.f, 0.f, 0.f);

    const int nc = (K + CHUNK - 1) / CHUNK;
    for (int c = 0; c < nc; ++c) {
        __syncthreads();   // protect target buffer (read finished last iter)
        if (c + 1 < nc)
            prefetch_chunk(W,  K,  O,  j0, (c+1)*CHUNK, slot ? bufA : bufB, tid);
        else
            prefetch_chunk(Wn, Kn, On, j0, 0,           slot ? bufA : bufB, tid);
        asm volatile("cp.async.wait_group 1;");   // chunk c has landed
        __syncthreads();

        const float* __restrict__ buf = slot ? bufB : bufA;
        const int base = c * CHUNK;
        const int rows = min(CHUNK, K - base);
        #pragma unroll
        for (int i = 0; i < CHUNK / (BLOCK/4); ++i) {
            const int r = kw + i * (BLOCK/4);
            if (r < rows) {
                const float  xv = xs[base + r];
                const float4 w  = *reinterpret_cast<const float4*>(buf + r*16 + jv*4);
                acc.x = fmaf(xv, w.x, acc.x);
                acc.y = fmaf(xv, w.y, acc.y);
                acc.z = fmaf(xv, w.z, acc.z);
                acc.w = fmaf(xv, w.w, acc.w);
            }
        }
        slot ^= 1;
    }

    // Intra-warp reduce over the 8 kw groups (lane bits 2..4)
    #pragma unroll
    for (int m = 4; m <= 16; m <<= 1) {
        acc.x += __shfl_xor_sync(0xffffffffu, acc.x, m);
        acc.y += __shfl_xor_sync(0xffffffffu, acc.y, m);
        acc.z += __shfl_xor_sync(0xffffffffu, acc.z, m);
        acc.w += __shfl_xor_sync(0xffffffffu, acc.w, m);
    }
    const int warp = tid >> 5;
    const int lane = tid & 31;
    if (lane < 4) red[warp][lane] = acc;
    __syncthreads();

    float4 r = make_float4(0.f, 0.f, 0.f, 0.f);
    if (tid < 32) {
        const int wi = tid >> 2;
        const int j  = tid & 3;
        const float4 a = red[wi][j];
        const float4 b = red[wi + 8][j];
        r.x = a.x + b.x; r.y = a.y + b.y; r.z = a.z + b.z; r.w = a.w + b.w;
        #pragma unroll
        for (int m = 4; m <= 16; m <<= 1) {
            r.x += __shfl_xor_sync(0xffffffffu, r.x, m);
            r.y += __shfl_xor_sync(0xffffffffu, r.y, m);
            r.z += __shfl_xor_sync(0xffffffffu, r.z, m);
            r.w += __shfl_xor_sync(0xffffffffu, r.w, m);
        }
    }
    return r;   // valid for tid < 4
}

__device__ __forceinline__ void store_hidden(float4 r,
        const float* __restrict__ bias, int O, float* __restrict__ out,
        int j0, int tid)
{
    if (tid < 4 && j0 < O) {
        const float4 b = __ldg(reinterpret_cast<const float4*>(bias + j0) + tid);
        r.x = fmaxf(r.x + b.x, 0.f);
        r.y = fmaxf(r.y + b.y, 0.f);
        r.z = fmaxf(r.z + b.z, 0.f);
        r.w = fmaxf(r.w + b.w, 0.f);
        reinterpret_cast<float4*>(out + j0)[tid] = r;
    }
}

// ---------------------------------------------------------------------------
// Init: reset barrier, seed x0 (+te(1) tail) + trajectory row 0, precompute te.
// ---------------------------------------------------------------------------
__global__ void init_kernel(
    const float* __restrict__ start,
    const float* __restrict__ te_w1, const float* __restrict__ te_b1,
    const float* __restrict__ te_w2, const float* __restrict__ te_b2,
    float* __restrict__ out)
{
    const int b   = blockIdx.x;     // 0..255
    const int tid = threadIdx.x;    // 128 threads
    if (b == 0) {
        if (tid == 0) g_count = 0u;
        for (int k = tid; k < GENE; k += TE) {
            const float v = start[k];
            g_x[0][k] = v;
            out[k]    = v;          // trajectory row 0
        }
    } else {
        const float t = (float)b * DT;
        __shared__ float h[TE];
        h[tid] = fmaxf(fmaf(t, te_w1[tid], te_b1[tid]), 0.f);
        __syncthreads();
        float acc = te_b2[tid];
        #pragma unroll 8
        for (int k = 0; k < TE; ++k)
            acc = fmaf(h[k], te_w2[k * TE + tid], acc);
        g_te[b][tid] = acc;
        if (b == 1) g_x[0][GENE + tid] = acc;   // te(1) tail for step 1
    }
}

// ---------------------------------------------------------------------------
// Persistent kernel: 255 Euler steps, 6 grid barriers per step, cp.async
// double-buffered weight streaming with cross-barrier prefetch.
// ---------------------------------------------------------------------------
__global__ void __launch_bounds__(BLOCK, 1) bridge_kernel(
    const float* __restrict__ w0, const float* __restrict__ b0,
    const float* __restrict__ w1, const float* __restrict__ b1,
    const float* __restrict__ w2, const float* __restrict__ b2,
    const float* __restrict__ w3, const float* __restrict__ b3,
    const float* __restrict__ w4, const float* __restrict__ b4,
    const float* __restrict__ wout, const float* __restrict__ bout,
    float* __restrict__ out)
{
    extern __shared__ float smem[];
    float* xs   = smem;                 // 2176 floats
    float* bufA = smem + 2176;          // CHUNK*16 floats
    float* bufB = bufA + CHUNK*16;
    __shared__ float4 red[16][4];

    const int tid = threadIdx.x;
    const int j0  = blockIdx.x * 16;
    unsigned nbar = 0;
    int slot = 0;

    // Prologue: chunk0 of step-1 layer0 into bufs[slot]
    prefetch_chunk(w0, KIN, HID, j0, 0, bufA, tid);

    for (int t = 1; t < NSTEP; ++t) {
        const float* xprev = g_x[(t - 1) & 1];
        float*       xcur  = g_x[t & 1];
        float4 r;

        r = layer_core(w0, KIN, HID,  w1, HID, HID,  xprev,
                       xs, bufA, bufB, slot, red, j0, tid, nbar);
        store_hidden(r, b0, HID, g_h0, j0, tid);

        r = layer_core(w1, HID, HID,  w2, HID, HID,  g_h0,
                       xs, bufA, bufB, slot, red, j0, tid, nbar);
        store_hidden(r, b1, HID, g_h1, j0, tid);

        r = layer_core(w2, HID, HID,  w3, HID, HID,  g_h1,
                       xs, bufA, bufB, slot, red, j0, tid, nbar);
        store_hidden(r, b2, HID, g_h0, j0, tid);

        r = layer_core(w3, HID, HID,  w4, HID, HID,  g_h0,
                       xs, bufA, bufB, slot, red, j0, tid, nbar);
        store_hidden(r, b3, HID, g_h1, j0, tid);

        r = layer_core(w4, HID, HID,  wout, HID, GENE,  g_h1,
                       xs, bufA, bufB, slot, red, j0, tid, nbar);
        store_hidden(r, b4, HID, g_h0, j0, tid);

        // Final layer + Euler update + trajectory store
        r = layer_core(wout, HID, GENE,  w0, KIN, HID,  g_h0,
                       xs, bufA, bufB, slot, red, j0, tid, nbar);
        if (tid < 4 && j0 < GENE) {
            const float4 b  = __ldg(reinterpret_cast<const float4*>(bout + j0) + tid);
            const float4 xp = __ldcg(reinterpret_cast<const float4*>(xprev + j0) + tid);
            float4 xn;
            xn.x = fmaf(r.x + b.x, DT, xp.x);
            xn.y = fmaf(r.y + b.y, DT, xp.y);
            xn.z = fmaf(r.z + b.z, DT, xp.z);
            xn.w = fmaf(r.w + b.w, DT, xp.w);
            reinterpret_cast<float4*>(xcur + j0)[tid] = xn;
            reinterpret_cast<float4*>(out + (size_t)t * GENE + j0)[tid] = xn;
        }
        // idle tail CTA installs te(t+1) into xcur tail for next step's layer0
        if (blockIdx.x == GRID - 1 && t + 1 < NSTEP && tid < TE)
            xcur[GENE + tid] = g_te[t + 1][tid];
    }
}

extern "C" void kernel_launch(void* const* d_in, const int* in_sizes, int n_in,
                              void* d_out, int out_size)
{
    (void)in_sizes; (void)n_in; (void)out_size;
    const float* start  = (const float*)d_in[0];
    // d_in[1] = end_state (unused)
    const float* te_w1  = (const float*)d_in[2];
    const float* te_b1  = (const float*)d_in[3];
    const float* te_w2  = (const float*)d_in[4];
    const float* te_b2  = (const float*)d_in[5];
    const float* w0     = (const float*)d_in[6];
    const float* b0     = (const float*)d_in[7];
    const float* w1     = (const float*)d_in[8];
    const float* b1     = (const float*)d_in[9];
    const float* w2     = (const float*)d_in[10];
    const float* b2     = (const float*)d_in[11];
    const float* w3     = (const float*)d_in[12];
    const float* b3     = (const float*)d_in[13];
    const float* w4     = (const float*)d_in[14];
    const float* b4     = (const float*)d_in[15];
    const float* wout   = (const float*)d_in[16];
    const float* bout   = (const float*)d_in[17];
    float* out = (float*)d_out;

    cudaFuncSetAttribute(bridge_kernel,
                         cudaFuncAttributeMaxDynamicSharedMemorySize, SMEM_BYTES);

    init_kernel<<<NSTEP, TE>>>(start, te_w1, te_b1, te_w2, te_b2, out);
    bridge_kernel<<<GRID, BLOCK, SMEM_BYTES>>>(w0, b0, w1, b1, w2, b2, w3, b3,
                                               w4, b4, wout, bout, out);
}